// round 7
// baseline (speedup 1.0000x reference)
#include <cuda_runtime.h>
#include <cstdint>
#include <math.h>

typedef unsigned int u32;

// Fully-fused NeRF forward, tf32 mma.sync, 3xTF32 trunk.
// R7: 512 threads / 16 warps (warp tile 32x64) for 2x latency hiding;
// WS=264 kills B-fragment bank conflicts; B-frags loaded inside nt-loop
// to cap register pressure at 512 threads/SM.

#define NRF_THREADS 512
#define NRF_TILE    128
#define NRF_HSTR    260   // h_s row stride (=4 mod 32: A-frag conflict-free)
#define NRF_ESTR    44
#define NRF_WS      264   // weight stage row stride (=8 mod 32: B conflict-free)
#define NRF_KC      16    // K rows per chunk

__device__ __forceinline__ float to_tf32(float x) {
    u32 u;
    asm("cvt.rna.tf32.f32 %0, %1;" : "=r"(u) : "f"(x));
    return __uint_as_float(u);
}
__device__ __forceinline__ u32 to_tf32_bits(float x) {
    u32 u;
    asm("cvt.rna.tf32.f32 %0, %1;" : "=r"(u) : "f"(x));
    return u;
}

__device__ __forceinline__ void mma8(float* d, const u32* a, const u32* b) {
    asm volatile(
        "mma.sync.aligned.m16n8k8.row.col.f32.tf32.tf32.f32 "
        "{%0,%1,%2,%3}, {%4,%5,%6,%7}, {%8,%9}, {%0,%1,%2,%3};\n"
        : "+f"(d[0]), "+f"(d[1]), "+f"(d[2]), "+f"(d[3])
        : "r"(a[0]), "r"(a[1]), "r"(a[2]), "r"(a[3]),
          "r"(b[0]), "r"(b[1]));
}

// =====================================================================
// 3xTF32 K-segment accumulation, 256 output cols (trunk).
// 512 threads stage: col = tid&255, rows (tid>>8)*8 + j.
// =====================================================================
__device__ __forceinline__ void accum3x_256(
    float acc[2][8][4],
    const float* __restrict__ Wg, int ldw, int co, int kwbase,
    const float* __restrict__ src, int sstr, int Kreal,
    float* __restrict__ wbuf0, float* __restrict__ wbuf1,
    int mbase, int n0, int tg, int tq, int tid)
{
    const int Kpad = (Kreal + 7) & ~7;
    const int nch  = (Kpad + NRF_KC - 1) / NRF_KC;
    const int scol = tid & 255;
    const int srow = (tid >> 8) * 8;

    #pragma unroll
    for (int j = 0; j < 8; j++) {
        const int kk = srow + j;
        wbuf0[(srow + j) * NRF_WS + scol] = (kk < Kreal)
            ? Wg[(size_t)(kwbase + kk) * ldw + co + scol] : 0.f;
    }
    __syncthreads();

    for (int ci = 0; ci < nch; ci++) {
        float* cur = (ci & 1) ? wbuf1 : wbuf0;
        float* nxt = (ci & 1) ? wbuf0 : wbuf1;
        const int k0 = ci * NRF_KC;
        const int kc = (NRF_KC < Kpad - k0) ? NRF_KC : (Kpad - k0);
        const bool have_next = (ci + 1 < nch);

        float pf[8];
        if (have_next) {
            const int kb = k0 + NRF_KC + srow;
            #pragma unroll
            for (int j = 0; j < 8; j++) {
                const int kk = kb + j;
                pf[j] = (kk < Kreal)
                    ? Wg[(size_t)(kwbase + kk) * ldw + co + scol] : 0.f;
            }
        }

        for (int ks = 0; ks < kc; ks += 8) {
            const int kabs = k0 + ks;
            // A fragments for both m-tiles (hi/lo split)
            u32 ah[2][4], al[2][4];
            #pragma unroll
            for (int mt = 0; mt < 2; mt++) {
                const float* sp = src + (mbase + mt * 16 + tg) * sstr + kabs + tq;
                const float a0 = sp[0];
                const float a1 = sp[8 * sstr];
                const float a2 = sp[4];
                const float a3 = sp[8 * sstr + 4];
                ah[mt][0] = to_tf32_bits(a0);
                ah[mt][1] = to_tf32_bits(a1);
                ah[mt][2] = to_tf32_bits(a2);
                ah[mt][3] = to_tf32_bits(a3);
                al[mt][0] = to_tf32_bits(a0 - __uint_as_float(ah[mt][0]));
                al[mt][1] = to_tf32_bits(a1 - __uint_as_float(ah[mt][1]));
                al[mt][2] = to_tf32_bits(a2 - __uint_as_float(ah[mt][2]));
                al[mt][3] = to_tf32_bits(a3 - __uint_as_float(ah[mt][3]));
            }
            #pragma unroll
            for (int nt = 0; nt < 8; nt++) {
                const int off = (ks + tq) * NRF_WS + n0 + nt * 8 + tg;
                const float w0 = cur[off];
                const float w1 = cur[off + 4 * NRF_WS];
                const float h0 = to_tf32(w0);
                const float h1 = to_tf32(w1);
                u32 bh[2], bl[2];
                bh[0] = __float_as_uint(h0);
                bh[1] = __float_as_uint(h1);
                bl[0] = to_tf32_bits(w0 - h0);
                bl[1] = to_tf32_bits(w1 - h1);
                #pragma unroll
                for (int mt = 0; mt < 2; mt++) {
                    mma8(acc[mt][nt], al[mt], bh);   // Alo*Bhi
                    mma8(acc[mt][nt], ah[mt], bl);   // Ahi*Blo
                    mma8(acc[mt][nt], ah[mt], bh);   // Ahi*Bhi
                }
            }
        }

        if (have_next) {
            #pragma unroll
            for (int j = 0; j < 8; j++)
                nxt[(srow + j) * NRF_WS + scol] = pf[j];
        }
        __syncthreads();
    }
}

// ---- single-pass tf32, 256 output cols (L7) ----
__device__ __forceinline__ void accum1x_256(
    float acc[2][8][4],
    const float* __restrict__ Wg, int ldw, int co, int kwbase,
    const float* __restrict__ src, int sstr, int Kreal,
    float* __restrict__ wbuf0, float* __restrict__ wbuf1,
    int mbase, int n0, int tg, int tq, int tid)
{
    const int Kpad = (Kreal + 7) & ~7;
    const int nch  = (Kpad + NRF_KC - 1) / NRF_KC;
    const int scol = tid & 255;
    const int srow = (tid >> 8) * 8;

    #pragma unroll
    for (int j = 0; j < 8; j++) {
        const int kk = srow + j;
        wbuf0[(srow + j) * NRF_WS + scol] = (kk < Kreal)
            ? Wg[(size_t)(kwbase + kk) * ldw + co + scol] : 0.f;
    }
    __syncthreads();

    for (int ci = 0; ci < nch; ci++) {
        float* cur = (ci & 1) ? wbuf1 : wbuf0;
        float* nxt = (ci & 1) ? wbuf0 : wbuf1;
        const int k0 = ci * NRF_KC;
        const int kc = (NRF_KC < Kpad - k0) ? NRF_KC : (Kpad - k0);
        const bool have_next = (ci + 1 < nch);

        float pf[8];
        if (have_next) {
            const int kb = k0 + NRF_KC + srow;
            #pragma unroll
            for (int j = 0; j < 8; j++) {
                const int kk = kb + j;
                pf[j] = (kk < Kreal)
                    ? Wg[(size_t)(kwbase + kk) * ldw + co + scol] : 0.f;
            }
        }

        for (int ks = 0; ks < kc; ks += 8) {
            const int kabs = k0 + ks;
            u32 afr[2][4];
            #pragma unroll
            for (int mt = 0; mt < 2; mt++) {
                const float* sp = src + (mbase + mt * 16 + tg) * sstr + kabs + tq;
                afr[mt][0] = to_tf32_bits(sp[0]);
                afr[mt][1] = to_tf32_bits(sp[8 * sstr]);
                afr[mt][2] = to_tf32_bits(sp[4]);
                afr[mt][3] = to_tf32_bits(sp[8 * sstr + 4]);
            }
            #pragma unroll
            for (int nt = 0; nt < 8; nt++) {
                const int off = (ks + tq) * NRF_WS + n0 + nt * 8 + tg;
                u32 bfr[2];
                bfr[0] = to_tf32_bits(cur[off]);
                bfr[1] = to_tf32_bits(cur[off + 4 * NRF_WS]);
                #pragma unroll
                for (int mt = 0; mt < 2; mt++)
                    mma8(acc[mt][nt], afr[mt], bfr);
            }
        }

        if (have_next) {
            #pragma unroll
            for (int j = 0; j < 8; j++)
                nxt[(srow + j) * NRF_WS + scol] = pf[j];
        }
        __syncthreads();
    }
}

// ---- single-pass tf32, 128 output cols (color head) ----
__device__ __forceinline__ void accum1x_128(
    float acc[2][4][4],
    const float* __restrict__ Wg, int kwbase,
    const float* __restrict__ src, int sstr, int Kreal,
    float* __restrict__ wbuf0, float* __restrict__ wbuf1,
    int mbase, int n0, int tg, int tq, int tid)
{
    const int Kpad = (Kreal + 7) & ~7;
    const int nch  = (Kpad + NRF_KC - 1) / NRF_KC;
    const int scol = tid & 127;
    const int srow = (tid >> 7) * 4;

    #pragma unroll
    for (int j = 0; j < 4; j++) {
        const int kk = srow + j;
        wbuf0[(srow + j) * NRF_WS + scol] = (kk < Kreal)
            ? Wg[(size_t)(kwbase + kk) * 128 + scol] : 0.f;
    }
    __syncthreads();

    for (int ci = 0; ci < nch; ci++) {
        float* cur = (ci & 1) ? wbuf1 : wbuf0;
        float* nxt = (ci & 1) ? wbuf0 : wbuf1;
        const int k0 = ci * NRF_KC;
        const int kc = (NRF_KC < Kpad - k0) ? NRF_KC : (Kpad - k0);
        const bool have_next = (ci + 1 < nch);

        float pf[4];
        if (have_next) {
            const int kb = k0 + NRF_KC + srow;
            #pragma unroll
            for (int j = 0; j < 4; j++) {
                const int kk = kb + j;
                pf[j] = (kk < Kreal)
                    ? Wg[(size_t)(kwbase + kk) * 128 + scol] : 0.f;
            }
        }

        for (int ks = 0; ks < kc; ks += 8) {
            const int kabs = k0 + ks;
            u32 afr[2][4];
            #pragma unroll
            for (int mt = 0; mt < 2; mt++) {
                const float* sp = src + (mbase + mt * 16 + tg) * sstr + kabs + tq;
                afr[mt][0] = to_tf32_bits(sp[0]);
                afr[mt][1] = to_tf32_bits(sp[8 * sstr]);
                afr[mt][2] = to_tf32_bits(sp[4]);
                afr[mt][3] = to_tf32_bits(sp[8 * sstr + 4]);
            }
            #pragma unroll
            for (int nt = 0; nt < 4; nt++) {
                const int off = (ks + tq) * NRF_WS + n0 + nt * 8 + tg;
                u32 bfr[2];
                bfr[0] = to_tf32_bits(cur[off]);
                bfr[1] = to_tf32_bits(cur[off + 4 * NRF_WS]);
                #pragma unroll
                for (int mt = 0; mt < 2; mt++)
                    mma8(acc[mt][nt], afr[mt], bfr);
            }
        }

        if (have_next) {
            #pragma unroll
            for (int j = 0; j < 4; j++)
                nxt[(srow + j) * NRF_WS + scol] = pf[j];
        }
        __syncthreads();
    }
}

// ---- Epilogues: bias + optional ReLU, write fp32 to SMEM ----
__device__ __forceinline__ void epilogue_256(
    float acc[2][8][4], const float* __restrict__ bg, int co,
    float* __restrict__ dst, bool relu,
    int mbase, int n0, int tg, int tq)
{
    #pragma unroll
    for (int nt = 0; nt < 8; nt++) {
        const int c = n0 + nt * 8 + 2 * tq;
        const float b0v = bg[co + c];
        const float b1v = bg[co + c + 1];
        #pragma unroll
        for (int mt = 0; mt < 2; mt++) {
            float v0 = acc[mt][nt][0] + b0v;
            float v1 = acc[mt][nt][1] + b1v;
            float v2 = acc[mt][nt][2] + b0v;
            float v3 = acc[mt][nt][3] + b1v;
            if (relu) {
                v0 = fmaxf(v0, 0.f); v1 = fmaxf(v1, 0.f);
                v2 = fmaxf(v2, 0.f); v3 = fmaxf(v3, 0.f);
            }
            const int r = mbase + mt * 16 + tg;
            *(float2*)(dst + r * NRF_HSTR + c)       = make_float2(v0, v1);
            *(float2*)(dst + (r + 8) * NRF_HSTR + c) = make_float2(v2, v3);
        }
    }
}

__device__ __forceinline__ void epilogue_128(
    float acc[2][4][4], const float* __restrict__ bg,
    float* __restrict__ dst,
    int mbase, int n0, int tg, int tq)
{
    #pragma unroll
    for (int nt = 0; nt < 4; nt++) {
        const int c = n0 + nt * 8 + 2 * tq;
        const float b0v = bg[c];
        const float b1v = bg[c + 1];
        #pragma unroll
        for (int mt = 0; mt < 2; mt++) {
            float v0 = fmaxf(acc[mt][nt][0] + b0v, 0.f);
            float v1 = fmaxf(acc[mt][nt][1] + b1v, 0.f);
            float v2 = fmaxf(acc[mt][nt][2] + b0v, 0.f);
            float v3 = fmaxf(acc[mt][nt][3] + b1v, 0.f);
            const int r = mbase + mt * 16 + tg;
            *(float2*)(dst + r * NRF_HSTR + c)       = make_float2(v0, v1);
            *(float2*)(dst + (r + 8) * NRF_HSTR + c) = make_float2(v2, v3);
        }
    }
}

__device__ __forceinline__ void zero_acc8(float acc[2][8][4]) {
    #pragma unroll
    for (int i = 0; i < 2; i++)
        #pragma unroll
        for (int j = 0; j < 8; j++)
            #pragma unroll
            for (int k = 0; k < 4; k++) acc[i][j][k] = 0.f;
}

__global__ void __launch_bounds__(NRF_THREADS, 1) nerf_tc_kernel(
    const float* __restrict__ pts, const float* __restrict__ dirs,
    const float* __restrict__ W0, const float* __restrict__ b0,
    const float* __restrict__ W1, const float* __restrict__ b1,
    const float* __restrict__ W2, const float* __restrict__ b2,
    const float* __restrict__ W3, const float* __restrict__ b3,
    const float* __restrict__ W4, const float* __restrict__ b4,
    const float* __restrict__ W5, const float* __restrict__ b5,
    const float* __restrict__ W6, const float* __restrict__ b6,
    const float* __restrict__ W7, const float* __restrict__ b7,
    const float* __restrict__ Wc, const float* __restrict__ bc,
    const float* __restrict__ Wo, const float* __restrict__ bo,
    float* __restrict__ out_color, float* __restrict__ out_sigma, int P)
{
    extern __shared__ float sm[];
    float* h_s   = sm;                           // [TILE][HSTR] activations fp32
    float* e_s   = h_s + NRF_TILE * NRF_HSTR;    // [TILE][ESTR] xyz emb -> dir emb
    float* wbuf0 = e_s + NRF_TILE * NRF_ESTR;    // [KC][WS] stage buffer 0
    float* wbuf1 = wbuf0 + NRF_KC * NRF_WS;      // [KC][WS] stage buffer 1

    const int tid  = threadIdx.x;
    const int warp = tid >> 5;
    const int lane = tid & 31;
    const int tg = lane >> 2;
    const int tq = lane & 3;
    const int mbase  = (warp >> 2) * 32;   // 4 m-groups of 32 rows
    const int n0_256 = (warp & 3) * 64;    // 4 n-groups of 64 cols
    const int n0_128 = (warp & 3) * 32;
    const int base = blockIdx.x * NRF_TILE;

    // ---- xyz harmonic embedding (one thread per point), fp32 ----
    if (tid < NRF_TILE) {
        const int n = base + tid;
        const float x = pts[n * 3 + 0];
        const float y = pts[n * 3 + 1];
        const float z = pts[n * 3 + 2];
        float* ep = e_s + tid * NRF_ESTR;
        #pragma unroll
        for (int h = 0; h < 6; h++) {
            const float f = (float)(1 << h);
            float sx, cx, sy, cy, sz, cz;
            sincosf(x * f, &sx, &cx);
            sincosf(y * f, &sy, &cy);
            sincosf(z * f, &sz, &cz);
            ep[0  + h] = sx; ep[6  + h] = sy; ep[12 + h] = sz;
            ep[18 + h] = cx; ep[24 + h] = cy; ep[30 + h] = cz;
        }
        ep[36] = x; ep[37] = y; ep[38] = z;
        #pragma unroll
        for (int c = 39; c < NRF_ESTR; c++) ep[c] = 0.f;
    }
    // (ordered by accum3x_256's chunk-0 stage barrier)

    float acc[2][8][4];

    // ---- L0: e(39) -> 256, ReLU (3xTF32) ----
    zero_acc8(acc);
    accum3x_256(acc, W0, 256, 0, 0, e_s, NRF_ESTR, 39, wbuf0, wbuf1, mbase, n0_256, tg, tq, tid);
    epilogue_256(acc, b0, 0, h_s, true, mbase, n0_256, tg, tq);

    // ---- L1..L4: 256 -> 256, ReLU (3xTF32) ----
    {
        const float* Ws[4] = {W1, W2, W3, W4};
        const float* bs[4] = {b1, b2, b3, b4};
        #pragma unroll 1
        for (int l = 0; l < 4; l++) {
            zero_acc8(acc);
            accum3x_256(acc, Ws[l], 256, 0, 0, h_s, NRF_HSTR, 256, wbuf0, wbuf1, mbase, n0_256, tg, tq, tid);
            epilogue_256(acc, bs[l], 0, h_s, true, mbase, n0_256, tg, tq);
        }
    }

    // ---- L5: [h(256), e(39)] -> 256, ReLU (3xTF32) ----
    zero_acc8(acc);
    accum3x_256(acc, W5, 256, 0, 0,   h_s, NRF_HSTR, 256, wbuf0, wbuf1, mbase, n0_256, tg, tq, tid);
    accum3x_256(acc, W5, 256, 0, 256, e_s, NRF_ESTR, 39,  wbuf0, wbuf1, mbase, n0_256, tg, tq, tid);
    epilogue_256(acc, b5, 0, h_s, true, mbase, n0_256, tg, tq);

    // ---- L6: 256 -> 256, ReLU (3xTF32) ----
    zero_acc8(acc);
    accum3x_256(acc, W6, 256, 0, 0, h_s, NRF_HSTR, 256, wbuf0, wbuf1, mbase, n0_256, tg, tq, tid);
    epilogue_256(acc, b6, 0, h_s, true, mbase, n0_256, tg, tq);

    __syncthreads();   // h6 fully written before sigma reads whole rows

    // ---- Sigma: col 0 of layer 7, from fp32 h6 (fp32 SIMT, reads only) ----
    if (tid < NRF_TILE) {
        float s = b7[0];
        const float* hp = h_s + tid * NRF_HSTR;
        #pragma unroll 4
        for (int k = 0; k < 256; k++) s = fmaf(hp[k], W7[k * 257], s);
        out_sigma[base + tid] = fmaxf(s, 0.f);
    }
    // (sigma reads done before L7's epilogue: L7 accum's barriers order them)

    // ---- L7 cols 1..256: 256 -> 256, no ReLU (single tf32) ----
    zero_acc8(acc);
    accum1x_256(acc, W7, 257, 1, 0, h_s, NRF_HSTR, 256, wbuf0, wbuf1, mbase, n0_256, tg, tq, tid);
    epilogue_256(acc, b7, 1, h_s, false, mbase, n0_256, tg, tq);

    // ---- dir harmonic embedding into e_s (e dead after L5) ----
    if (tid < NRF_TILE) {
        const int n = base + tid;
        const int r = n / P;
        const float dx = dirs[r * 3 + 0];
        const float dy = dirs[r * 3 + 1];
        const float dz = dirs[r * 3 + 2];
        float* dp = e_s + tid * NRF_ESTR;
        #pragma unroll
        for (int h = 0; h < 4; h++) {
            const float f = (float)(1 << h);
            float sx, cx, sy, cy, sz, cz;
            sincosf(dx * f, &sx, &cx);
            sincosf(dy * f, &sy, &cy);
            sincosf(dz * f, &sz, &cz);
            dp[0  + h] = sx; dp[4  + h] = sy; dp[8  + h] = sz;
            dp[12 + h] = cx; dp[16 + h] = cy; dp[20 + h] = cz;
        }
        dp[24] = dx; dp[25] = dy; dp[26] = dz;
        #pragma unroll
        for (int c = 27; c < 32; c++) dp[c] = 0.f;   // zero pad to Kpad=32
    }
    // (ordered before use by head accum's stage barrier)

    // ---- Color head: [h7(256), d(27)] -> 128, ReLU (single tf32) ----
    {
        float acc2[2][4][4];
        #pragma unroll
        for (int i = 0; i < 2; i++)
            #pragma unroll
            for (int j = 0; j < 4; j++)
                #pragma unroll
                for (int k = 0; k < 4; k++) acc2[i][j][k] = 0.f;
        accum1x_128(acc2, Wc, 0,   h_s, NRF_HSTR, 256, wbuf0, wbuf1, mbase, n0_128, tg, tq, tid);
        accum1x_128(acc2, Wc, 256, e_s, NRF_ESTR, 27,  wbuf0, wbuf1, mbase, n0_128, tg, tq, tid);
        epilogue_128(acc2, bc, h_s, mbase, n0_128, tg, tq);
    }

    __syncthreads();   // head output fully written before final reads

    // ---- Output: sigmoid(h @ Wo + bo), 3 cols per point (384 pairs) ----
    for (int idx = tid; idx < NRF_TILE * 3; idx += NRF_THREADS) {
        const int p = idx / 3;
        const int c = idx - p * 3;
        float s = bo[c];
        const float* hp = h_s + p * NRF_HSTR;
        #pragma unroll 4
        for (int k = 0; k < 128; k++) s = fmaf(hp[k], Wo[k * 3 + c], s);
        out_color[(base + p) * 3 + c] = 1.f / (1.f + expf(-s));
    }
}

extern "C" void kernel_launch(void* const* d_in, const int* in_sizes, int n_in,
                              void* d_out, int out_size)
{
    const float* pts  = (const float*)d_in[0];
    const float* dirs = (const float*)d_in[1];
    const float* W0 = (const float*)d_in[2];   const float* b0 = (const float*)d_in[3];
    const float* W1 = (const float*)d_in[4];   const float* b1 = (const float*)d_in[5];
    const float* W2 = (const float*)d_in[6];   const float* b2 = (const float*)d_in[7];
    const float* W3 = (const float*)d_in[8];   const float* b3 = (const float*)d_in[9];
    const float* W4 = (const float*)d_in[10];  const float* b4 = (const float*)d_in[11];
    const float* W5 = (const float*)d_in[12];  const float* b5 = (const float*)d_in[13];
    const float* W6 = (const float*)d_in[14];  const float* b6 = (const float*)d_in[15];
    const float* W7 = (const float*)d_in[16];  const float* b7 = (const float*)d_in[17];
    const float* Wc = (const float*)d_in[18];  const float* bc = (const float*)d_in[19];
    const float* Wo = (const float*)d_in[20];  const float* bo = (const float*)d_in[21];

    const int N = in_sizes[0] / 3;        // 131072 points
    const int R = in_sizes[1] / 3;        // 2048 rays
    const int P = N / R;                  // 64 samples per ray

    float* out_color = (float*)d_out;               // [N,3] first (tuple order)
    float* out_sigma = out_color + (size_t)N * 3;   // [N,1] after

    const int smem_bytes = (NRF_TILE * NRF_HSTR + NRF_TILE * NRF_ESTR +
                            2 * NRF_KC * NRF_WS) * (int)sizeof(float);
    cudaFuncSetAttribute(nerf_tc_kernel,
                         cudaFuncAttributeMaxDynamicSharedMemorySize, smem_bytes);

    nerf_tc_kernel<<<N / NRF_TILE, NRF_THREADS, smem_bytes>>>(
        pts, dirs,
        W0, b0, W1, b1, W2, b2, W3, b3, W4, b4, W5, b5, W6, b6, W7, b7,
        Wc, bc, Wo, bo,
        out_color, out_sigma, P);
}

// round 8
// speedup vs baseline: 1.6762x; 1.6762x over previous
#include <cuda_runtime.h>
#include <cuda_bf16.h>
#include <cstdint>
#include <math.h>

typedef unsigned int u32;
typedef __nv_bfloat16 bf16;

// Fully-fused NeRF forward. Trunk = bf16x3 split-precision (residual 2^-18,
// ~fp32-grade through 7 layers) on mma.sync.m16n8k16.bf16 — half the HMMA
// count of tf32 k8 at 2x rate. L7 + color head = single-pass bf16.
// Activations stored PRE-SPLIT as (hi, lo) bf16 arrays; weights staged
// pre-split and TRANSPOSED [N][K] so B-fragments are aligned u32 loads.
// 256 threads, 8 warps (2m x 4n), warp tile 64x64, ping-pong staging.

#define NRF_THREADS 256
#define NRF_TILE    128
#define HSB 264   // h row stride in bf16 (132 words = 4 mod 32: conflict-free)
#define ESB 56    // e row stride in bf16 (28 words mod 32: conflict-free)
#define WTS 18    // transposed weight-stage row stride in bf16 (9 words: ~free)
#define KC  16    // K rows per staged chunk (= one k16 mma step)

__device__ __forceinline__ void mma16(float* d, const u32* a, const u32* b) {
    asm volatile(
        "mma.sync.aligned.m16n8k16.row.col.f32.bf16.bf16.f32 "
        "{%0,%1,%2,%3}, {%4,%5,%6,%7}, {%8,%9}, {%0,%1,%2,%3};\n"
        : "+f"(d[0]), "+f"(d[1]), "+f"(d[2]), "+f"(d[3])
        : "r"(a[0]), "r"(a[1]), "r"(a[2]), "r"(a[3]),
          "r"(b[0]), "r"(b[1]));
}

__device__ __forceinline__ u32 pack2(bf16 a, bf16 b) {
    __nv_bfloat162 p;
    p.x = a; p.y = b;           // .x = lower address = lower 16 bits
    return *reinterpret_cast<u32*>(&p);
}

__device__ __forceinline__ void bsplit(float v, bf16& h, bf16& l) {
    h = __float2bfloat16_rn(v);
    l = __float2bfloat16_rn(v - __bfloat162float(h));
}

// =====================================================================
// bf16x3 K-segment accumulation, 256 output cols (trunk).
// Staging: thread tid owns output column tid; stages KC=16 k-rows
// transposed into wb[col][k] (hi & lo). Ping-pong + register prefetch.
// =====================================================================
__device__ __forceinline__ void accum3x_256(
    float acc[4][8][4],
    const float* __restrict__ Wg, int ldw, int co, int kwbase,
    const bf16* __restrict__ src_hi, const bf16* __restrict__ src_lo,
    int sstr, int Kreal,
    bf16* __restrict__ wh0, bf16* __restrict__ wl0,
    bf16* __restrict__ wh1, bf16* __restrict__ wl1,
    int mbase, int n0, int tg, int tq, int tid)
{
    const int Kpad = (Kreal + 15) & ~15;
    const int nch  = Kpad / KC;
    const int scol = tid;

    // stage chunk 0 (transposed, pre-split)
    #pragma unroll
    for (int j = 0; j < KC; j += 2) {
        const float w0 = (j     < Kreal) ? Wg[(size_t)(kwbase + j    ) * ldw + co + scol] : 0.f;
        const float w1 = (j + 1 < Kreal) ? Wg[(size_t)(kwbase + j + 1) * ldw + co + scol] : 0.f;
        bf16 h0, l0, h1, l1;
        bsplit(w0, h0, l0);
        bsplit(w1, h1, l1);
        *(u32*)(wh0 + scol * WTS + j) = pack2(h0, h1);
        *(u32*)(wl0 + scol * WTS + j) = pack2(l0, l1);
    }
    __syncthreads();

    for (int ci = 0; ci < nch; ci++) {
        bf16* chi = (ci & 1) ? wh1 : wh0;
        bf16* clo = (ci & 1) ? wl1 : wl0;
        bf16* nhi = (ci & 1) ? wh0 : wh1;
        bf16* nlo = (ci & 1) ? wl0 : wl1;
        const int k0 = ci * KC;
        const bool have_next = (ci + 1 < nch);

        // prefetch next chunk (raw fp32) into registers
        float pf[KC];
        if (have_next) {
            const int kb = k0 + KC;
            #pragma unroll
            for (int j = 0; j < KC; j++) {
                const int kk = kb + j;
                pf[j] = (kk < Kreal)
                    ? Wg[(size_t)(kwbase + kk) * ldw + co + scol] : 0.f;
            }
        }

        // A fragments (hi/lo), held across nt loop
        u32 ah[4][4], al[4][4];
        #pragma unroll
        for (int mt = 0; mt < 4; mt++) {
            const int r = mbase + mt * 16 + tg;
            const bf16* ph = src_hi + r * sstr + k0 + 2 * tq;
            const bf16* pl = src_lo + r * sstr + k0 + 2 * tq;
            ah[mt][0] = *(const u32*)(ph);
            ah[mt][1] = *(const u32*)(ph + 8 * sstr);
            ah[mt][2] = *(const u32*)(ph + 8);
            ah[mt][3] = *(const u32*)(ph + 8 * sstr + 8);
            al[mt][0] = *(const u32*)(pl);
            al[mt][1] = *(const u32*)(pl + 8 * sstr);
            al[mt][2] = *(const u32*)(pl + 8);
            al[mt][3] = *(const u32*)(pl + 8 * sstr + 8);
        }

        #pragma unroll
        for (int nt = 0; nt < 8; nt++) {
            const int nn = n0 + nt * 8 + tg;
            const bf16* pbh = chi + nn * WTS + 2 * tq;
            const bf16* pbl = clo + nn * WTS + 2 * tq;
            u32 bh[2], bl[2];
            bh[0] = *(const u32*)(pbh);
            bh[1] = *(const u32*)(pbh + 8);
            bl[0] = *(const u32*)(pbl);
            bl[1] = *(const u32*)(pbl + 8);
            #pragma unroll
            for (int mt = 0; mt < 4; mt++) {
                mma16(acc[mt][nt], al[mt], bh);   // Alo*Bhi
                mma16(acc[mt][nt], ah[mt], bl);   // Ahi*Blo
                mma16(acc[mt][nt], ah[mt], bh);   // Ahi*Bhi
            }
        }

        if (have_next) {
            #pragma unroll
            for (int j = 0; j < KC; j += 2) {
                bf16 h0, l0, h1, l1;
                bsplit(pf[j],     h0, l0);
                bsplit(pf[j + 1], h1, l1);
                *(u32*)(nhi + scol * WTS + j) = pack2(h0, h1);
                *(u32*)(nlo + scol * WTS + j) = pack2(l0, l1);
            }
        }
        __syncthreads();
    }
}

// ---- single-pass bf16, 256 output cols (L7). Uses hi arrays only. ----
__device__ __forceinline__ void accum1x_256(
    float acc[4][8][4],
    const float* __restrict__ Wg, int ldw, int co, int kwbase,
    const bf16* __restrict__ src_hi, int sstr, int Kreal,
    bf16* __restrict__ wh0, bf16* __restrict__ wh1,
    int mbase, int n0, int tg, int tq, int tid)
{
    const int Kpad = (Kreal + 15) & ~15;
    const int nch  = Kpad / KC;
    const int scol = tid;

    #pragma unroll
    for (int j = 0; j < KC; j += 2) {
        const float w0 = (j     < Kreal) ? Wg[(size_t)(kwbase + j    ) * ldw + co + scol] : 0.f;
        const float w1 = (j + 1 < Kreal) ? Wg[(size_t)(kwbase + j + 1) * ldw + co + scol] : 0.f;
        *(u32*)(wh0 + scol * WTS + j) =
            pack2(__float2bfloat16_rn(w0), __float2bfloat16_rn(w1));
    }
    __syncthreads();

    for (int ci = 0; ci < nch; ci++) {
        bf16* chi = (ci & 1) ? wh1 : wh0;
        bf16* nhi = (ci & 1) ? wh0 : wh1;
        const int k0 = ci * KC;
        const bool have_next = (ci + 1 < nch);

        float pf[KC];
        if (have_next) {
            const int kb = k0 + KC;
            #pragma unroll
            for (int j = 0; j < KC; j++) {
                const int kk = kb + j;
                pf[j] = (kk < Kreal)
                    ? Wg[(size_t)(kwbase + kk) * ldw + co + scol] : 0.f;
            }
        }

        u32 ah[4][4];
        #pragma unroll
        for (int mt = 0; mt < 4; mt++) {
            const int r = mbase + mt * 16 + tg;
            const bf16* ph = src_hi + r * sstr + k0 + 2 * tq;
            ah[mt][0] = *(const u32*)(ph);
            ah[mt][1] = *(const u32*)(ph + 8 * sstr);
            ah[mt][2] = *(const u32*)(ph + 8);
            ah[mt][3] = *(const u32*)(ph + 8 * sstr + 8);
        }

        #pragma unroll
        for (int nt = 0; nt < 8; nt++) {
            const int nn = n0 + nt * 8 + tg;
            const bf16* pbh = chi + nn * WTS + 2 * tq;
            u32 bh[2];
            bh[0] = *(const u32*)(pbh);
            bh[1] = *(const u32*)(pbh + 8);
            #pragma unroll
            for (int mt = 0; mt < 4; mt++)
                mma16(acc[mt][nt], ah[mt], bh);
        }

        if (have_next) {
            #pragma unroll
            for (int j = 0; j < KC; j += 2) {
                *(u32*)(nhi + scol * WTS + j) =
                    pack2(__float2bfloat16_rn(pf[j]), __float2bfloat16_rn(pf[j + 1]));
            }
        }
        __syncthreads();
    }
}

// ---- single-pass bf16, 128 output cols (color head) ----
__device__ __forceinline__ void accum1x_128(
    float acc[4][4][4],
    const float* __restrict__ Wg, int kwbase,
    const bf16* __restrict__ src_hi, int sstr, int Kreal,
    bf16* __restrict__ wh0, bf16* __restrict__ wh1,
    int mbase, int n0, int tg, int tq, int tid)
{
    const int Kpad = (Kreal + 15) & ~15;
    const int nch  = Kpad / KC;
    const int scol = tid & 127;
    const int kh   = (tid >> 7) * 8;   // rows kh..kh+7 of the 16-row chunk

    #pragma unroll
    for (int j = 0; j < 8; j += 2) {
        const int ka = kh + j;
        const float w0 = (ka     < Kreal) ? Wg[(size_t)(kwbase + ka    ) * 128 + scol] : 0.f;
        const float w1 = (ka + 1 < Kreal) ? Wg[(size_t)(kwbase + ka + 1) * 128 + scol] : 0.f;
        *(u32*)(wh0 + scol * WTS + ka) =
            pack2(__float2bfloat16_rn(w0), __float2bfloat16_rn(w1));
    }
    __syncthreads();

    for (int ci = 0; ci < nch; ci++) {
        bf16* chi = (ci & 1) ? wh1 : wh0;
        bf16* nhi = (ci & 1) ? wh0 : wh1;
        const int k0 = ci * KC;
        const bool have_next = (ci + 1 < nch);

        float pf[8];
        if (have_next) {
            const int kb = k0 + KC + kh;
            #pragma unroll
            for (int j = 0; j < 8; j++) {
                const int kk = kb + j;
                pf[j] = (kk < Kreal)
                    ? Wg[(size_t)(kwbase + kk) * 128 + scol] : 0.f;
            }
        }

        u32 ah[4][4];
        #pragma unroll
        for (int mt = 0; mt < 4; mt++) {
            const int r = mbase + mt * 16 + tg;
            const bf16* ph = src_hi + r * sstr + k0 + 2 * tq;
            ah[mt][0] = *(const u32*)(ph);
            ah[mt][1] = *(const u32*)(ph + 8 * sstr);
            ah[mt][2] = *(const u32*)(ph + 8);
            ah[mt][3] = *(const u32*)(ph + 8 * sstr + 8);
        }

        #pragma unroll
        for (int nt = 0; nt < 4; nt++) {
            const int nn = n0 + nt * 8 + tg;
            const bf16* pbh = chi + nn * WTS + 2 * tq;
            u32 bh[2];
            bh[0] = *(const u32*)(pbh);
            bh[1] = *(const u32*)(pbh + 8);
            #pragma unroll
            for (int mt = 0; mt < 4; mt++)
                mma16(acc[mt][nt], ah[mt], bh);
        }

        if (have_next) {
            #pragma unroll
            for (int j = 0; j < 8; j += 2) {
                *(u32*)(nhi + scol * WTS + kh + j) =
                    pack2(__float2bfloat16_rn(pf[j]), __float2bfloat16_rn(pf[j + 1]));
            }
        }
        __syncthreads();
    }
}

// ---- Epilogues: bias + optional ReLU, pre-split hi/lo write to SMEM ----
__device__ __forceinline__ void epilogue_256(
    float acc[4][8][4], const float* __restrict__ bg, int co,
    bf16* __restrict__ dst_hi, bf16* __restrict__ dst_lo, bool relu,
    int mbase, int n0, int tg, int tq)
{
    #pragma unroll
    for (int nt = 0; nt < 8; nt++) {
        const int c = n0 + nt * 8 + 2 * tq;
        const float b0v = bg[co + c];
        const float b1v = bg[co + c + 1];
        #pragma unroll
        for (int mt = 0; mt < 4; mt++) {
            float v0 = acc[mt][nt][0] + b0v;
            float v1 = acc[mt][nt][1] + b1v;
            float v2 = acc[mt][nt][2] + b0v;
            float v3 = acc[mt][nt][3] + b1v;
            if (relu) {
                v0 = fmaxf(v0, 0.f); v1 = fmaxf(v1, 0.f);
                v2 = fmaxf(v2, 0.f); v3 = fmaxf(v3, 0.f);
            }
            const int r = mbase + mt * 16 + tg;
            bf16 h0, l0, h1, l1;
            bsplit(v0, h0, l0); bsplit(v1, h1, l1);
            *(u32*)(dst_hi + r * HSB + c) = pack2(h0, h1);
            *(u32*)(dst_lo + r * HSB + c) = pack2(l0, l1);
            bsplit(v2, h0, l0); bsplit(v3, h1, l1);
            *(u32*)(dst_hi + (r + 8) * HSB + c) = pack2(h0, h1);
            *(u32*)(dst_lo + (r + 8) * HSB + c) = pack2(l0, l1);
        }
    }
}

__device__ __forceinline__ void epilogue_128(
    float acc[4][4][4], const float* __restrict__ bg,
    bf16* __restrict__ dst_hi, bf16* __restrict__ dst_lo,
    int mbase, int n0, int tg, int tq)
{
    #pragma unroll
    for (int nt = 0; nt < 4; nt++) {
        const int c = n0 + nt * 8 + 2 * tq;
        const float b0v = bg[c];
        const float b1v = bg[c + 1];
        #pragma unroll
        for (int mt = 0; mt < 4; mt++) {
            float v0 = fmaxf(acc[mt][nt][0] + b0v, 0.f);
            float v1 = fmaxf(acc[mt][nt][1] + b1v, 0.f);
            float v2 = fmaxf(acc[mt][nt][2] + b0v, 0.f);
            float v3 = fmaxf(acc[mt][nt][3] + b1v, 0.f);
            const int r = mbase + mt * 16 + tg;
            bf16 h0, l0, h1, l1;
            bsplit(v0, h0, l0); bsplit(v1, h1, l1);
            *(u32*)(dst_hi + r * HSB + c) = pack2(h0, h1);
            *(u32*)(dst_lo + r * HSB + c) = pack2(l0, l1);
            bsplit(v2, h0, l0); bsplit(v3, h1, l1);
            *(u32*)(dst_hi + (r + 8) * HSB + c) = pack2(h0, h1);
            *(u32*)(dst_lo + (r + 8) * HSB + c) = pack2(l0, l1);
        }
    }
}

__device__ __forceinline__ void zero_acc8(float acc[4][8][4]) {
    #pragma unroll
    for (int i = 0; i < 4; i++)
        #pragma unroll
        for (int j = 0; j < 8; j++)
            #pragma unroll
            for (int k = 0; k < 4; k++) acc[i][j][k] = 0.f;
}

__global__ void __launch_bounds__(NRF_THREADS, 1) nerf_tc_kernel(
    const float* __restrict__ pts, const float* __restrict__ dirs,
    const float* __restrict__ W0, const float* __restrict__ b0,
    const float* __restrict__ W1, const float* __restrict__ b1,
    const float* __restrict__ W2, const float* __restrict__ b2,
    const float* __restrict__ W3, const float* __restrict__ b3,
    const float* __restrict__ W4, const float* __restrict__ b4,
    const float* __restrict__ W5, const float* __restrict__ b5,
    const float* __restrict__ W6, const float* __restrict__ b6,
    const float* __restrict__ W7, const float* __restrict__ b7,
    const float* __restrict__ Wc, const float* __restrict__ bc,
    const float* __restrict__ Wo, const float* __restrict__ bo,
    float* __restrict__ out_color, float* __restrict__ out_sigma, int P)
{
    extern __shared__ char smc[];
    bf16* h_hi = (bf16*)smc;                    // [128][HSB]
    bf16* h_lo = h_hi + NRF_TILE * HSB;
    bf16* e_hi = h_lo + NRF_TILE * HSB;         // [128][ESB]
    bf16* e_lo = e_hi + NRF_TILE * ESB;
    bf16* wh0  = e_lo + NRF_TILE * ESB;         // [256][WTS] transposed stage
    bf16* wl0  = wh0 + 256 * WTS;
    bf16* wh1  = wl0 + 256 * WTS;
    bf16* wl1  = wh1 + 256 * WTS;

    const int tid  = threadIdx.x;
    const int warp = tid >> 5;
    const int lane = tid & 31;
    const int tg = lane >> 2;
    const int tq = lane & 3;
    const int mbase  = (warp >> 2) * 64;
    const int n0_256 = (warp & 3) * 64;
    const int n0_128 = (warp & 3) * 32;
    const int base = blockIdx.x * NRF_TILE;

    // ---- xyz harmonic embedding, written pre-split (hi/lo bf16) ----
    if (tid < NRF_TILE) {
        const int n = base + tid;
        const float x = pts[n * 3 + 0];
        const float y = pts[n * 3 + 1];
        const float z = pts[n * 3 + 2];
        bf16* eh = e_hi + tid * ESB;
        bf16* el = e_lo + tid * ESB;
        #pragma unroll
        for (int h = 0; h < 6; h++) {
            const float f = (float)(1 << h);
            float sx, cx, sy, cy, sz, cz;
            sincosf(x * f, &sx, &cx);
            sincosf(y * f, &sy, &cy);
            sincosf(z * f, &sz, &cz);
            bf16 hh, ll;
            bsplit(sx, hh, ll); eh[0  + h] = hh; el[0  + h] = ll;
            bsplit(sy, hh, ll); eh[6  + h] = hh; el[6  + h] = ll;
            bsplit(sz, hh, ll); eh[12 + h] = hh; el[12 + h] = ll;
            bsplit(cx, hh, ll); eh[18 + h] = hh; el[18 + h] = ll;
            bsplit(cy, hh, ll); eh[24 + h] = hh; el[24 + h] = ll;
            bsplit(cz, hh, ll); eh[30 + h] = hh; el[30 + h] = ll;
        }
        bf16 hh, ll;
        bsplit(x, hh, ll); eh[36] = hh; el[36] = ll;
        bsplit(y, hh, ll); eh[37] = hh; el[37] = ll;
        bsplit(z, hh, ll); eh[38] = hh; el[38] = ll;
        const bf16 zb = __float2bfloat16_rn(0.f);
        #pragma unroll
        for (int c = 39; c < 48; c++) { eh[c] = zb; el[c] = zb; }
    }
    // (ordered by accum's chunk-0 stage barrier)

    float acc[4][8][4];

    // ---- L0: e(39) -> 256, ReLU (bf16x3) ----
    zero_acc8(acc);
    accum3x_256(acc, W0, 256, 0, 0, e_hi, e_lo, ESB, 39,
                wh0, wl0, wh1, wl1, mbase, n0_256, tg, tq, tid);
    epilogue_256(acc, b0, 0, h_hi, h_lo, true, mbase, n0_256, tg, tq);

    // ---- L1..L4: 256 -> 256, ReLU (bf16x3) ----
    {
        const float* Ws[4] = {W1, W2, W3, W4};
        const float* bs[4] = {b1, b2, b3, b4};
        #pragma unroll 1
        for (int l = 0; l < 4; l++) {
            zero_acc8(acc);
            accum3x_256(acc, Ws[l], 256, 0, 0, h_hi, h_lo, HSB, 256,
                        wh0, wl0, wh1, wl1, mbase, n0_256, tg, tq, tid);
            epilogue_256(acc, bs[l], 0, h_hi, h_lo, true, mbase, n0_256, tg, tq);
        }
    }

    // ---- L5: [h(256), e(39)] -> 256, ReLU (bf16x3) ----
    zero_acc8(acc);
    accum3x_256(acc, W5, 256, 0, 0,   h_hi, h_lo, HSB, 256,
                wh0, wl0, wh1, wl1, mbase, n0_256, tg, tq, tid);
    accum3x_256(acc, W5, 256, 0, 256, e_hi, e_lo, ESB, 39,
                wh0, wl0, wh1, wl1, mbase, n0_256, tg, tq, tid);
    epilogue_256(acc, b5, 0, h_hi, h_lo, true, mbase, n0_256, tg, tq);

    // ---- L6: 256 -> 256, ReLU (bf16x3) ----
    zero_acc8(acc);
    accum3x_256(acc, W6, 256, 0, 0, h_hi, h_lo, HSB, 256,
                wh0, wl0, wh1, wl1, mbase, n0_256, tg, tq, tid);
    epilogue_256(acc, b6, 0, h_hi, h_lo, true, mbase, n0_256, tg, tq);

    __syncthreads();   // h6 fully written before sigma reads whole rows

    // ---- Sigma: col 0 of layer 7, from reconstructed h6 (fp32 SIMT) ----
    if (tid < NRF_TILE) {
        float s = b7[0];
        const bf16* ph = h_hi + tid * HSB;
        const bf16* pl = h_lo + tid * HSB;
        #pragma unroll 4
        for (int k = 0; k < 256; k++) {
            const float hv = __bfloat162float(ph[k]) + __bfloat162float(pl[k]);
            s = fmaf(hv, W7[k * 257], s);
        }
        out_sigma[base + tid] = fmaxf(s, 0.f);
    }
    // (sigma reads finish before L7 epilogue: L7 accum's barriers order them)

    // ---- L7 cols 1..256 (no ReLU, single bf16; A = h_hi) ----
    zero_acc8(acc);
    accum1x_256(acc, W7, 257, 1, 0, h_hi, HSB, 256,
                wh0, wh1, mbase, n0_256, tg, tq, tid);
    epilogue_256(acc, b7, 1, h_hi, h_lo, false, mbase, n0_256, tg, tq);

    // ---- dir harmonic embedding into e arrays (e dead after L5) ----
    if (tid < NRF_TILE) {
        const int n = base + tid;
        const int r = n / P;
        const float dx = dirs[r * 3 + 0];
        const float dy = dirs[r * 3 + 1];
        const float dz = dirs[r * 3 + 2];
        bf16* eh = e_hi + tid * ESB;
        bf16* el = e_lo + tid * ESB;
        #pragma unroll
        for (int h = 0; h < 4; h++) {
            const float f = (float)(1 << h);
            float sx, cx, sy, cy, sz, cz;
            sincosf(dx * f, &sx, &cx);
            sincosf(dy * f, &sy, &cy);
            sincosf(dz * f, &sz, &cz);
            bf16 hh, ll;
            bsplit(sx, hh, ll); eh[0  + h] = hh; el[0  + h] = ll;
            bsplit(sy, hh, ll); eh[4  + h] = hh; el[4  + h] = ll;
            bsplit(sz, hh, ll); eh[8  + h] = hh; el[8  + h] = ll;
            bsplit(cx, hh, ll); eh[12 + h] = hh; el[12 + h] = ll;
            bsplit(cy, hh, ll); eh[16 + h] = hh; el[16 + h] = ll;
            bsplit(cz, hh, ll); eh[20 + h] = hh; el[20 + h] = ll;
        }
        bf16 hh, ll;
        bsplit(dx, hh, ll); eh[24] = hh; el[24] = ll;
        bsplit(dy, hh, ll); eh[25] = hh; el[25] = ll;
        bsplit(dz, hh, ll); eh[26] = hh; el[26] = ll;
        const bf16 zb = __float2bfloat16_rn(0.f);
        #pragma unroll
        for (int c = 27; c < 32; c++) { eh[c] = zb; el[c] = zb; }
    }
    // (ordered before use by head accum's stage barrier)

    // ---- Color head: [h7(256), d(27)] -> 128, ReLU (single bf16) ----
    {
        float acc2[4][4][4];
        #pragma unroll
        for (int i = 0; i < 4; i++)
            #pragma unroll
            for (int j = 0; j < 4; j++)
                #pragma unroll
                for (int k = 0; k < 4; k++) acc2[i][j][k] = 0.f;
        accum1x_128(acc2, Wc, 0,   h_hi, HSB, 256,
                    wh0, wh1, mbase, n0_128, tg, tq, tid);
        accum1x_128(acc2, Wc, 256, e_hi, ESB, 27,
                    wh0, wh1, mbase, n0_128, tg, tq, tid);
        epilogue_128(acc2, bc, h_hi, h_lo, mbase, n0_128, tg, tq);
    }

    __syncthreads();   // head output fully written before final reads

    // ---- Output: sigmoid(h @ Wo + bo), 3 cols per point (384 pairs) ----
    for (int idx = tid; idx < NRF_TILE * 3; idx += NRF_THREADS) {
        const int p = idx / 3;
        const int c = idx - p * 3;
        float s = bo[c];
        const bf16* ph = h_hi + p * HSB;
        const bf16* pl = h_lo + p * HSB;
        #pragma unroll 4
        for (int k = 0; k < 128; k++) {
            const float hv = __bfloat162float(ph[k]) + __bfloat162float(pl[k]);
            s = fmaf(hv, Wo[k * 3 + c], s);
        }
        out_color[(base + p) * 3 + c] = 1.f / (1.f + expf(-s));
    }
}

extern "C" void kernel_launch(void* const* d_in, const int* in_sizes, int n_in,
                              void* d_out, int out_size)
{
    const float* pts  = (const float*)d_in[0];
    const float* dirs = (const float*)d_in[1];
    const float* W0 = (const float*)d_in[2];   const float* b0 = (const float*)d_in[3];
    const float* W1 = (const float*)d_in[4];   const float* b1 = (const float*)d_in[5];
    const float* W2 = (const float*)d_in[6];   const float* b2 = (const float*)d_in[7];
    const float* W3 = (const float*)d_in[8];   const float* b3 = (const float*)d_in[9];
    const float* W4 = (const float*)d_in[10];  const float* b4 = (const float*)d_in[11];
    const float* W5 = (const float*)d_in[12];  const float* b5 = (const float*)d_in[13];
    const float* W6 = (const float*)d_in[14];  const float* b6 = (const float*)d_in[15];
    const float* W7 = (const float*)d_in[16];  const float* b7 = (const float*)d_in[17];
    const float* Wc = (const float*)d_in[18];  const float* bc = (const float*)d_in[19];
    const float* Wo = (const float*)d_in[20];  const float* bo = (const float*)d_in[21];

    const int N = in_sizes[0] / 3;        // 131072 points
    const int R = in_sizes[1] / 3;        // 2048 rays
    const int P = N / R;                  // 64 samples per ray

    float* out_color = (float*)d_out;               // [N,3] first (tuple order)
    float* out_sigma = out_color + (size_t)N * 3;   // [N,1] after

    const int smem_bytes = (NRF_TILE * HSB * 2 + NRF_TILE * ESB * 2 +
                            256 * WTS * 4) * (int)sizeof(bf16);
    cudaFuncSetAttribute(nerf_tc_kernel,
                         cudaFuncAttributeMaxDynamicSharedMemorySize, smem_bytes);

    nerf_tc_kernel<<<N / NRF_TILE, NRF_THREADS, smem_bytes>>>(
        pts, dirs,
        W0, b0, W1, b1, W2, b2, W3, b3, W4, b4, W5, b5, W6, b6, W7, b7,
        Wc, bc, Wo, bo,
        out_color, out_sigma, P);
}